// round 2
// baseline (speedup 1.0000x reference)
#include <cuda_runtime.h>
#include <math.h>

#define N_NODES 50000
#define N_EDGES 800000

// ---------------- static device scratch (allocation-free rule) ----------------
__device__ float g_bufA[N_NODES * 256];
__device__ float g_bufB[N_NODES * 256];
__device__ int   g_rowoff[N_NODES + 1];
__device__ int   g_cursor[N_NODES];
__device__ int   g_cnt[N_NODES];
__device__ float g_dinv[N_NODES];
__device__ float g_ns[N_NODES];
__device__ int   g_col[N_EDGES];
__device__ float g_val[N_EDGES];

// ---------------- CSR build ----------------
__global__ void zero_cnt_kernel() {
    int i = blockIdx.x * blockDim.x + threadIdx.x;
    if (i < N_NODES) g_cnt[i] = 0;
}

// edge_index is int32 (JAX x64 disabled: jnp.int64 -> int32)
__global__ void hist_kernel(const int* __restrict__ ei) {
    int e = blockIdx.x * blockDim.x + threadIdx.x;
    if (e < N_EDGES) {
        int d = ei[N_EDGES + e];
        atomicAdd(&g_cnt[d], 1);
    }
}

__global__ void dinv_kernel() {
    int i = blockIdx.x * blockDim.x + threadIdx.x;
    if (i < N_NODES) {
        float deg = (float)g_cnt[i] + 1.0f;
        float di = rsqrtf(deg);
        g_dinv[i] = di;
        g_ns[i] = di * di;
    }
}

// single-block exclusive scan of g_cnt -> g_rowoff (+ copy to g_cursor)
__global__ void scan_kernel() {
    __shared__ int warp_sums[32];
    const int tid = threadIdx.x;
    const int lane = tid & 31, wid = tid >> 5;
    const int nwarps = blockDim.x >> 5;
    int base = 0;
    for (int start = 0; start < N_NODES; start += blockDim.x) {
        int i = start + tid;
        int x = (i < N_NODES) ? g_cnt[i] : 0;
        // warp inclusive scan
        int v = x;
        #pragma unroll
        for (int o = 1; o < 32; o <<= 1) {
            int t = __shfl_up_sync(0xFFFFFFFFu, v, o);
            if (lane >= o) v += t;
        }
        if (lane == 31) warp_sums[wid] = v;
        __syncthreads();
        if (wid == 0) {
            int w = (lane < nwarps) ? warp_sums[lane] : 0;
            #pragma unroll
            for (int o = 1; o < 32; o <<= 1) {
                int t = __shfl_up_sync(0xFFFFFFFFu, w, o);
                if (lane >= o) w += t;
            }
            warp_sums[lane] = w;
        }
        __syncthreads();
        int warp_excl = (wid > 0) ? warp_sums[wid - 1] : 0;
        int excl = v + warp_excl - x;
        if (i < N_NODES) {
            g_rowoff[i] = base + excl;
            g_cursor[i] = base + excl;
        }
        base += warp_sums[nwarps - 1];
        __syncthreads();
    }
    if (tid == 0) g_rowoff[N_NODES] = base;
}

__global__ void scatter_kernel(const int* __restrict__ ei) {
    int e = blockIdx.x * blockDim.x + threadIdx.x;
    if (e < N_EDGES) {
        int s = ei[e];
        int d = ei[N_EDGES + e];
        int pos = atomicAdd(&g_cursor[d], 1);
        g_col[pos] = s;
        g_val[pos] = g_dinv[s] * g_dinv[d];
    }
}

// ---------------- GEMM: C = A[N x K] @ W[K x Dout]  (+ bias, + act) ----------------
// BM=64, BN=64, BK=16, 256 threads, 4x4 microtile
template <int ACT>  // 0 none, 1 relu
__global__ void gemm_kernel(const float* __restrict__ A, const float* __restrict__ W,
                            const float* __restrict__ bias, float* __restrict__ C,
                            int K, int Dout) {
    __shared__ __align__(16) float As[16][68];
    __shared__ __align__(16) float Bs[16][64];
    const int t  = threadIdx.x;
    const int tx = t & 15, ty = t >> 4;
    const int rowBase = blockIdx.x * 64;
    const int colBase = blockIdx.y * 64;

    const int ar = t >> 2, akc = (t & 3) * 4;   // A load: row, k-chunk
    const int bk = t >> 4, bc = (t & 15) * 4;   // W load: k, col-chunk

    float acc[4][4] = {};

    for (int k0 = 0; k0 < K; k0 += 16) {
        float4 a = make_float4(0.f, 0.f, 0.f, 0.f);
        if (rowBase + ar < N_NODES)
            a = *reinterpret_cast<const float4*>(&A[(size_t)(rowBase + ar) * K + k0 + akc]);
        As[akc + 0][ar] = a.x;
        As[akc + 1][ar] = a.y;
        As[akc + 2][ar] = a.z;
        As[akc + 3][ar] = a.w;
        *reinterpret_cast<float4*>(&Bs[bk][bc]) =
            *reinterpret_cast<const float4*>(&W[(size_t)(k0 + bk) * Dout + colBase + bc]);
        __syncthreads();
        #pragma unroll
        for (int k = 0; k < 16; k++) {
            float4 av = *reinterpret_cast<const float4*>(&As[k][ty * 4]);
            float4 bv = *reinterpret_cast<const float4*>(&Bs[k][tx * 4]);
            float aa[4] = {av.x, av.y, av.z, av.w};
            float bb[4] = {bv.x, bv.y, bv.z, bv.w};
            #pragma unroll
            for (int i = 0; i < 4; i++)
                #pragma unroll
                for (int j = 0; j < 4; j++)
                    acc[i][j] += aa[i] * bb[j];
        }
        __syncthreads();
    }

    #pragma unroll
    for (int i = 0; i < 4; i++) {
        int r = rowBase + ty * 4 + i;
        if (r < N_NODES) {
            float4 v;
            float* vp = &v.x;
            #pragma unroll
            for (int j = 0; j < 4; j++) {
                int c = colBase + tx * 4 + j;
                float x = acc[i][j];
                if (bias) x += bias[c];
                if (ACT == 1) x = fmaxf(x, 0.f);
                vp[j] = x;
            }
            *reinterpret_cast<float4*>(&C[(size_t)r * Dout + colBase + tx * 4]) = v;
        }
    }
}

// ---------------- Aggregation: out[i] = ns[i]*in[i] + sum_e w_e * in[src_e] (+bias,+act) ----------------
template <int D, int ACT>  // ACT: 0 none, 1 relu, 2 sigmoid
__global__ void agg_kernel(const float* __restrict__ in, float* __restrict__ out,
                           const float* __restrict__ bias) {
    int warp = (blockIdx.x * blockDim.x + threadIdx.x) >> 5;
    if (warp >= N_NODES) return;
    int lane = threadIdx.x & 31;
    constexpr int V = D / 32;
    float acc[V];
    float s = g_ns[warp];
    const float* self = in + (size_t)warp * D;
    #pragma unroll
    for (int v = 0; v < V; v++) acc[v] = s * self[lane + v * 32];

    int beg = g_rowoff[warp], end = g_rowoff[warp + 1];
    for (int e = beg; e < end; e++) {
        int sidx = g_col[e];
        float w = g_val[e];
        const float* p = in + (size_t)sidx * D;
        #pragma unroll
        for (int v = 0; v < V; v++) acc[v] += w * p[lane + v * 32];
    }

    float* o = out + (size_t)warp * D;
    #pragma unroll
    for (int v = 0; v < V; v++) {
        float r = acc[v];
        if (bias) r += bias[lane + v * 32];
        if (ACT == 1) r = fmaxf(r, 0.f);
        if (ACT == 2) r = 1.0f / (1.0f + expf(-r));
        o[lane + v * 32] = r;
    }
}

// ---------------- launch ----------------
extern "C" void kernel_launch(void* const* d_in, const int* in_sizes, int n_in,
                              void* d_out, int out_size) {
    const float* x  = (const float*)d_in[0];
    const int*   ei = (const int*)d_in[1];   // int32! (JAX x64 disabled)
    const float* W1 = (const float*)d_in[2],  *b1 = (const float*)d_in[3];
    const float* W2 = (const float*)d_in[4],  *b2 = (const float*)d_in[5];
    const float* W3 = (const float*)d_in[6],  *b3 = (const float*)d_in[7];
    const float* W4 = (const float*)d_in[8],  *b4 = (const float*)d_in[9];
    const float* W5 = (const float*)d_in[10], *b5 = (const float*)d_in[11];
    const float* W6 = (const float*)d_in[12], *b6 = (const float*)d_in[13];
    float* out = (float*)d_out;

    float *bufA, *bufB;
    cudaGetSymbolAddress((void**)&bufA, g_bufA);
    cudaGetSymbolAddress((void**)&bufB, g_bufB);

    const int TB = 256;
    const int nodeBlocks = (N_NODES + TB - 1) / TB;
    const int edgeBlocks = (N_EDGES + TB - 1) / TB;
    const int aggBlocks  = (N_NODES * 32 + TB - 1) / TB;
    const int gemmRows   = (N_NODES + 63) / 64;

    // ---- preprocessing: degrees + CSR by dst ----
    zero_cnt_kernel<<<nodeBlocks, TB>>>();
    hist_kernel<<<edgeBlocks, TB>>>(ei);
    dinv_kernel<<<nodeBlocks, TB>>>();
    scan_kernel<<<1, 1024>>>();
    scatter_kernel<<<edgeBlocks, TB>>>(ei);

    // L1: (128->64), aggregate AFTER matmul
    gemm_kernel<0><<<dim3(gemmRows, 1), TB>>>(x, W1, nullptr, bufA, 128, 64);
    agg_kernel<64, 1><<<aggBlocks, TB>>>(bufA, bufB, b1);

    // L2: (64->128), aggregate BEFORE matmul
    agg_kernel<64, 0><<<aggBlocks, TB>>>(bufB, bufA, nullptr);
    gemm_kernel<1><<<dim3(gemmRows, 2), TB>>>(bufA, W2, b2, bufB, 64, 128);

    // L3: (128->256), aggregate BEFORE matmul
    agg_kernel<128, 0><<<aggBlocks, TB>>>(bufB, bufA, nullptr);
    gemm_kernel<1><<<dim3(gemmRows, 4), TB>>>(bufA, W3, b3, bufB, 128, 256);

    // L4: (256->128), aggregate AFTER matmul
    gemm_kernel<0><<<dim3(gemmRows, 2), TB>>>(bufB, W4, nullptr, bufA, 256, 128);
    agg_kernel<128, 1><<<aggBlocks, TB>>>(bufA, bufB, b4);

    // L5: (128->64), aggregate AFTER matmul
    gemm_kernel<0><<<dim3(gemmRows, 1), TB>>>(bufB, W5, nullptr, bufA, 128, 64);
    agg_kernel<64, 1><<<aggBlocks, TB>>>(bufA, bufB, b5);

    // L6: (64->64), aggregate AFTER matmul, sigmoid, write d_out
    gemm_kernel<0><<<dim3(gemmRows, 1), TB>>>(bufB, W6, nullptr, bufA, 64, 64);
    agg_kernel<64, 2><<<aggBlocks, TB>>>(bufA, out, b6);
}

// round 3
// speedup vs baseline: 1.1402x; 1.1402x over previous
#include <cuda_runtime.h>
#include <math.h>

#define N_NODES 50000
#define N_EDGES 800000

// ---------------- static device scratch (allocation-free rule) ----------------
__device__ float g_bufA[N_NODES * 256];
__device__ float g_bufB[N_NODES * 256];
__device__ int   g_rowbeg[N_NODES];
__device__ int   g_rowend[N_NODES];
__device__ int   g_cursor[N_NODES];
__device__ int   g_cnt[N_NODES];
__device__ float g_dinv[N_NODES];
__device__ float g_ns[N_NODES];
__device__ int   g_col[N_EDGES];
__device__ float g_val[N_EDGES];
__device__ int   g_total;

// ---------------- CSR build (scan-free: atomic segment allocation) ----------------
__global__ void zero_cnt_kernel() {
    int i = blockIdx.x * blockDim.x + threadIdx.x;
    if (i < N_NODES) g_cnt[i] = 0;
    if (i == 0) g_total = 0;
}

// edge_index is int32 (JAX x64 disabled: jnp.int64 -> int32)
__global__ void hist_kernel(const int* __restrict__ ei) {
    int e = blockIdx.x * blockDim.x + threadIdx.x;
    if (e < N_EDGES) {
        int d = ei[N_EDGES + e];
        atomicAdd(&g_cnt[d], 1);
    }
}

// degree norm + claim a contiguous CSR segment per node via atomic bump
__global__ void alloc_kernel() {
    int i = blockIdx.x * blockDim.x + threadIdx.x;
    if (i < N_NODES) {
        int c = g_cnt[i];
        float deg = (float)c + 1.0f;
        float di = rsqrtf(deg);
        g_dinv[i] = di;
        g_ns[i] = di * di;
        int beg = atomicAdd(&g_total, c);
        g_rowbeg[i] = beg;
        g_rowend[i] = beg + c;
        g_cursor[i] = beg;
    }
}

__global__ void scatter_kernel(const int* __restrict__ ei) {
    int e = blockIdx.x * blockDim.x + threadIdx.x;
    if (e < N_EDGES) {
        int s = ei[e];
        int d = ei[N_EDGES + e];
        int pos = atomicAdd(&g_cursor[d], 1);
        g_col[pos] = s;
        g_val[pos] = g_dinv[s] * g_dinv[d];
    }
}

// ---------------- GEMM: C = A[N x K] @ W[K x Dout]  (+ bias, + act) ----------------
// BM=128, BN=64, BK=16, 256 threads, 8x4 microtile, double-buffered SMEM
template <int ACT>  // 0 none, 1 relu
__global__ void __launch_bounds__(256) gemm_kernel(
    const float* __restrict__ A, const float* __restrict__ W,
    const float* __restrict__ bias, float* __restrict__ C,
    int K, int Dout) {
    __shared__ __align__(16) float As[2][16][132];
    __shared__ __align__(16) float Bs[2][16][64];
    const int t  = threadIdx.x;
    const int tx = t & 15, ty = t >> 4;
    const int rowBase = blockIdx.x * 128;
    const int colBase = blockIdx.y * 64;

    // A load: each thread loads 2 float4 along K for one row
    const int ar  = t >> 1;          // 0..127
    const int akc = (t & 1) * 8;     // k-chunk base 0 or 8
    // W load: one float4
    const int bk = ty, bc = tx * 4;

    float acc[8][4] = {};
    const int KT = K >> 4;

    float4 a0, a1, b0;
    // prefetch tile 0
    {
        int grow = rowBase + ar;
        if (grow < N_NODES) {
            const float* ap = &A[(size_t)grow * K + akc];
            a0 = *reinterpret_cast<const float4*>(ap);
            a1 = *reinterpret_cast<const float4*>(ap + 4);
        } else {
            a0 = make_float4(0.f,0.f,0.f,0.f); a1 = a0;
        }
        b0 = *reinterpret_cast<const float4*>(&W[(size_t)bk * Dout + colBase + bc]);
    }
    // store tile 0
    As[0][akc+0][ar] = a0.x; As[0][akc+1][ar] = a0.y;
    As[0][akc+2][ar] = a0.z; As[0][akc+3][ar] = a0.w;
    As[0][akc+4][ar] = a1.x; As[0][akc+5][ar] = a1.y;
    As[0][akc+6][ar] = a1.z; As[0][akc+7][ar] = a1.w;
    *reinterpret_cast<float4*>(&Bs[0][bk][bc]) = b0;
    __syncthreads();

    int cur = 0;
    for (int kt = 0; kt < KT; kt++) {
        if (kt + 1 < KT) {
            int k0 = (kt + 1) * 16;
            int grow = rowBase + ar;
            if (grow < N_NODES) {
                const float* ap = &A[(size_t)grow * K + k0 + akc];
                a0 = *reinterpret_cast<const float4*>(ap);
                a1 = *reinterpret_cast<const float4*>(ap + 4);
            } else {
                a0 = make_float4(0.f,0.f,0.f,0.f); a1 = a0;
            }
            b0 = *reinterpret_cast<const float4*>(&W[(size_t)(k0 + bk) * Dout + colBase + bc]);
        }
        #pragma unroll
        for (int k = 0; k < 16; k++) {
            float4 av0 = *reinterpret_cast<const float4*>(&As[cur][k][ty * 8]);
            float4 av1 = *reinterpret_cast<const float4*>(&As[cur][k][ty * 8 + 4]);
            float4 bv  = *reinterpret_cast<const float4*>(&Bs[cur][k][tx * 4]);
            float aa[8] = {av0.x, av0.y, av0.z, av0.w, av1.x, av1.y, av1.z, av1.w};
            float bb[4] = {bv.x, bv.y, bv.z, bv.w};
            #pragma unroll
            for (int i = 0; i < 8; i++)
                #pragma unroll
                for (int j = 0; j < 4; j++)
                    acc[i][j] += aa[i] * bb[j];
        }
        if (kt + 1 < KT) {
            int nxt = cur ^ 1;
            As[nxt][akc+0][ar] = a0.x; As[nxt][akc+1][ar] = a0.y;
            As[nxt][akc+2][ar] = a0.z; As[nxt][akc+3][ar] = a0.w;
            As[nxt][akc+4][ar] = a1.x; As[nxt][akc+5][ar] = a1.y;
            As[nxt][akc+6][ar] = a1.z; As[nxt][akc+7][ar] = a1.w;
            *reinterpret_cast<float4*>(&Bs[nxt][bk][bc]) = b0;
            __syncthreads();
            cur = nxt;
        }
    }

    #pragma unroll
    for (int i = 0; i < 8; i++) {
        int r = rowBase + ty * 8 + i;
        if (r < N_NODES) {
            float4 v;
            float* vp = &v.x;
            #pragma unroll
            for (int j = 0; j < 4; j++) {
                float x = acc[i][j];
                if (bias) x += bias[colBase + tx * 4 + j];
                if (ACT == 1) x = fmaxf(x, 0.f);
                vp[j] = x;
            }
            *reinterpret_cast<float4*>(&C[(size_t)r * Dout + colBase + tx * 4]) = v;
        }
    }
}

// ---------------- Aggregation D=64: lane owns float2 ----------------
template <int ACT>  // 0 none, 1 relu, 2 sigmoid
__global__ void __launch_bounds__(256) agg64_kernel(
    const float* __restrict__ in, float* __restrict__ out,
    const float* __restrict__ bias) {
    int warp = (blockIdx.x * blockDim.x + threadIdx.x) >> 5;
    if (warp >= N_NODES) return;
    int lane = threadIdx.x & 31;
    const int off = lane * 2;

    float s = g_ns[warp];
    float2 self = *reinterpret_cast<const float2*>(in + (size_t)warp * 64 + off);
    float ax = s * self.x, ay = s * self.y;

    int e = g_rowbeg[warp], end = g_rowend[warp];
    for (; e + 4 <= end; e += 4) {
        int s0 = g_col[e], s1 = g_col[e+1], s2 = g_col[e+2], s3 = g_col[e+3];
        float w0 = g_val[e], w1 = g_val[e+1], w2 = g_val[e+2], w3 = g_val[e+3];
        float2 p0 = *reinterpret_cast<const float2*>(in + (size_t)s0 * 64 + off);
        float2 p1 = *reinterpret_cast<const float2*>(in + (size_t)s1 * 64 + off);
        float2 p2 = *reinterpret_cast<const float2*>(in + (size_t)s2 * 64 + off);
        float2 p3 = *reinterpret_cast<const float2*>(in + (size_t)s3 * 64 + off);
        ax += w0 * p0.x; ay += w0 * p0.y;
        ax += w1 * p1.x; ay += w1 * p1.y;
        ax += w2 * p2.x; ay += w2 * p2.y;
        ax += w3 * p3.x; ay += w3 * p3.y;
    }
    for (; e < end; e++) {
        int si = g_col[e]; float w = g_val[e];
        float2 p = *reinterpret_cast<const float2*>(in + (size_t)si * 64 + off);
        ax += w * p.x; ay += w * p.y;
    }

    if (bias) {
        const float2 b = *reinterpret_cast<const float2*>(bias + off);
        ax += b.x; ay += b.y;
    }
    if (ACT == 1) { ax = fmaxf(ax, 0.f); ay = fmaxf(ay, 0.f); }
    if (ACT == 2) {
        ax = 1.0f / (1.0f + expf(-ax));
        ay = 1.0f / (1.0f + expf(-ay));
    }
    *reinterpret_cast<float2*>(out + (size_t)warp * 64 + off) = make_float2(ax, ay);
}

// ---------------- Aggregation D=128: lane owns float4 ----------------
template <int ACT>
__global__ void __launch_bounds__(256) agg128_kernel(
    const float* __restrict__ in, float* __restrict__ out,
    const float* __restrict__ bias) {
    int warp = (blockIdx.x * blockDim.x + threadIdx.x) >> 5;
    if (warp >= N_NODES) return;
    int lane = threadIdx.x & 31;
    const int off = lane * 4;

    float s = g_ns[warp];
    float4 self = *reinterpret_cast<const float4*>(in + (size_t)warp * 128 + off);
    float ax = s*self.x, ay = s*self.y, az = s*self.z, aw = s*self.w;

    int e = g_rowbeg[warp], end = g_rowend[warp];
    for (; e + 4 <= end; e += 4) {
        int s0 = g_col[e], s1 = g_col[e+1], s2 = g_col[e+2], s3 = g_col[e+3];
        float w0 = g_val[e], w1 = g_val[e+1], w2 = g_val[e+2], w3 = g_val[e+3];
        float4 p0 = *reinterpret_cast<const float4*>(in + (size_t)s0 * 128 + off);
        float4 p1 = *reinterpret_cast<const float4*>(in + (size_t)s1 * 128 + off);
        float4 p2 = *reinterpret_cast<const float4*>(in + (size_t)s2 * 128 + off);
        float4 p3 = *reinterpret_cast<const float4*>(in + (size_t)s3 * 128 + off);
        ax += w0*p0.x; ay += w0*p0.y; az += w0*p0.z; aw += w0*p0.w;
        ax += w1*p1.x; ay += w1*p1.y; az += w1*p1.z; aw += w1*p1.w;
        ax += w2*p2.x; ay += w2*p2.y; az += w2*p2.z; aw += w2*p2.w;
        ax += w3*p3.x; ay += w3*p3.y; az += w3*p3.z; aw += w3*p3.w;
    }
    for (; e < end; e++) {
        int si = g_col[e]; float w = g_val[e];
        float4 p = *reinterpret_cast<const float4*>(in + (size_t)si * 128 + off);
        ax += w*p.x; ay += w*p.y; az += w*p.z; aw += w*p.w;
    }

    if (bias) {
        const float4 b = *reinterpret_cast<const float4*>(bias + off);
        ax += b.x; ay += b.y; az += b.z; aw += b.w;
    }
    if (ACT == 1) {
        ax = fmaxf(ax, 0.f); ay = fmaxf(ay, 0.f);
        az = fmaxf(az, 0.f); aw = fmaxf(aw, 0.f);
    }
    if (ACT == 2) {
        ax = 1.0f/(1.0f+expf(-ax)); ay = 1.0f/(1.0f+expf(-ay));
        az = 1.0f/(1.0f+expf(-az)); aw = 1.0f/(1.0f+expf(-aw));
    }
    *reinterpret_cast<float4*>(out + (size_t)warp * 128 + off) = make_float4(ax, ay, az, aw);
}

// ---------------- launch ----------------
extern "C" void kernel_launch(void* const* d_in, const int* in_sizes, int n_in,
                              void* d_out, int out_size) {
    const float* x  = (const float*)d_in[0];
    const int*   ei = (const int*)d_in[1];   // int32! (JAX x64 disabled)
    const float* W1 = (const float*)d_in[2],  *b1 = (const float*)d_in[3];
    const float* W2 = (const float*)d_in[4],  *b2 = (const float*)d_in[5];
    const float* W3 = (const float*)d_in[6],  *b3 = (const float*)d_in[7];
    const float* W4 = (const float*)d_in[8],  *b4 = (const float*)d_in[9];
    const float* W5 = (const float*)d_in[10], *b5 = (const float*)d_in[11];
    const float* W6 = (const float*)d_in[12], *b6 = (const float*)d_in[13];
    float* out = (float*)d_out;

    float *bufA, *bufB;
    cudaGetSymbolAddress((void**)&bufA, g_bufA);
    cudaGetSymbolAddress((void**)&bufB, g_bufB);

    const int TB = 256;
    const int nodeBlocks = (N_NODES + TB - 1) / TB;
    const int edgeBlocks = (N_EDGES + TB - 1) / TB;
    const int aggBlocks  = (N_NODES * 32 + TB - 1) / TB;
    const int gemmRows   = (N_NODES + 127) / 128;

    // ---- preprocessing: degrees + CSR by dst (scan-free) ----
    zero_cnt_kernel<<<nodeBlocks, TB>>>();
    hist_kernel<<<edgeBlocks, TB>>>(ei);
    alloc_kernel<<<nodeBlocks, TB>>>();
    scatter_kernel<<<edgeBlocks, TB>>>(ei);

    // L1: (128->64), aggregate AFTER matmul
    gemm_kernel<0><<<dim3(gemmRows, 1), TB>>>(x, W1, nullptr, bufA, 128, 64);
    agg64_kernel<1><<<aggBlocks, TB>>>(bufA, bufB, b1);

    // L2: (64->128), aggregate BEFORE matmul
    agg64_kernel<0><<<aggBlocks, TB>>>(bufB, bufA, nullptr);
    gemm_kernel<1><<<dim3(gemmRows, 2), TB>>>(bufA, W2, b2, bufB, 64, 128);

    // L3: (128->256), aggregate BEFORE matmul
    agg128_kernel<0><<<aggBlocks, TB>>>(bufB, bufA, nullptr);
    gemm_kernel<1><<<dim3(gemmRows, 4), TB>>>(bufA, W3, b3, bufB, 128, 256);

    // L4: (256->128), aggregate AFTER matmul
    gemm_kernel<0><<<dim3(gemmRows, 2), TB>>>(bufB, W4, nullptr, bufA, 256, 128);
    agg128_kernel<1><<<aggBlocks, TB>>>(bufA, bufB, b4);

    // L5: (128->64), aggregate AFTER matmul
    gemm_kernel<0><<<dim3(gemmRows, 1), TB>>>(bufB, W5, nullptr, bufA, 128, 64);
    agg64_kernel<1><<<aggBlocks, TB>>>(bufA, bufB, b5);

    // L6: (64->64), aggregate AFTER matmul, sigmoid, write d_out
    gemm_kernel<0><<<dim3(gemmRows, 1), TB>>>(bufB, W6, nullptr, bufA, 64, 64);
    agg64_kernel<2><<<aggBlocks, TB>>>(bufA, out, b6);
}

// round 4
// speedup vs baseline: 1.2063x; 1.0579x over previous
#include <cuda_runtime.h>
#include <math.h>

#define N_NODES 50000
#define N_EDGES 800000

// ---------------- static device scratch (allocation-free rule) ----------------
__device__ float g_bufA[N_NODES * 256];
__device__ float g_bufB[N_NODES * 256];
__device__ int   g_rowbeg[N_NODES];
__device__ int   g_rowend[N_NODES];
__device__ int   g_cursor[N_NODES];
__device__ int   g_cnt[N_NODES];
__device__ float g_dinv[N_NODES];
__device__ float g_ns[N_NODES];
__device__ unsigned long long g_edge[N_EDGES];  // packed: hi32=val bits, lo32=col
__device__ int   g_total;

// ---------------- CSR build (scan-free: atomic segment allocation) ----------------
__global__ void zero_cnt_kernel() {
    int i = blockIdx.x * blockDim.x + threadIdx.x;
    if (i < N_NODES) g_cnt[i] = 0;
    if (i == 0) g_total = 0;
}

// edge_index is int32 (JAX x64 disabled: jnp.int64 -> int32)
__global__ void hist_kernel(const int* __restrict__ ei) {
    int e = blockIdx.x * blockDim.x + threadIdx.x;
    if (e < N_EDGES) {
        int d = ei[N_EDGES + e];
        atomicAdd(&g_cnt[d], 1);
    }
}

// degree norm + claim a contiguous CSR segment per node via atomic bump
__global__ void alloc_kernel() {
    int i = blockIdx.x * blockDim.x + threadIdx.x;
    if (i < N_NODES) {
        int c = g_cnt[i];
        float deg = (float)c + 1.0f;
        float di = rsqrtf(deg);
        g_dinv[i] = di;
        g_ns[i] = di * di;
        int beg = atomicAdd(&g_total, c);
        g_rowbeg[i] = beg;
        g_rowend[i] = beg + c;
        g_cursor[i] = beg;
    }
}

__global__ void scatter_kernel(const int* __restrict__ ei) {
    int e = blockIdx.x * blockDim.x + threadIdx.x;
    if (e < N_EDGES) {
        int s = ei[e];
        int d = ei[N_EDGES + e];
        int pos = atomicAdd(&g_cursor[d], 1);
        float w = g_dinv[s] * g_dinv[d];
        unsigned long long pk =
            ((unsigned long long)__float_as_uint(w) << 32) | (unsigned int)s;
        g_edge[pos] = pk;
    }
}

// ---------------- packed dual-fp32 FMA (Blackwell FFMA2) ----------------
__device__ __forceinline__ void ffma2(unsigned long long& acc,
                                      unsigned long long a,
                                      unsigned long long b) {
    asm("fma.rn.f32x2 %0, %1, %2, %0;" : "+l"(acc) : "l"(a), "l"(b));
}
__device__ __forceinline__ unsigned long long pack2(unsigned int lo, unsigned int hi) {
    unsigned long long r;
    asm("mov.b64 %0, {%1, %2};" : "=l"(r) : "r"(lo), "r"(hi));
    return r;
}
__device__ __forceinline__ void unpack2(unsigned long long v, unsigned int& lo, unsigned int& hi) {
    asm("mov.b64 {%0, %1}, %2;" : "=r"(lo), "=r"(hi) : "l"(v));
}

// ---------------- GEMM: C = A[N x K] @ W[K x Dout]  (+ bias, + act) ----------------
// BM=128, BN=64, BK=16, 256 threads, 8x4 microtile via 4x4 packed-f32x2,
// double-buffered SMEM
template <int ACT>  // 0 none, 1 relu
__global__ void __launch_bounds__(256) gemm_kernel(
    const float* __restrict__ A, const float* __restrict__ W,
    const float* __restrict__ bias, float* __restrict__ C,
    int K, int Dout) {
    __shared__ __align__(16) float As[2][16][132];
    __shared__ __align__(16) float Bs[2][16][64];
    const int t  = threadIdx.x;
    const int tx = t & 15, ty = t >> 4;
    const int rowBase = blockIdx.x * 128;
    const int colBase = blockIdx.y * 64;

    // A load: each thread loads 2 float4 along K for one row
    const int ar  = t >> 1;          // 0..127
    const int akc = (t & 1) * 8;     // k-chunk base 0 or 8
    // W load: one float4
    const int bk = ty, bc = tx * 4;

    // acc[ip][j]: packed pair of rows (ty*8+2ip, ty*8+2ip+1), col j
    unsigned long long acc[4][4] = {};
    const int KT = K >> 4;

    float4 a0, a1, b0;
    // prefetch tile 0
    {
        int grow = rowBase + ar;
        if (grow < N_NODES) {
            const float* ap = &A[(size_t)grow * K + akc];
            a0 = *reinterpret_cast<const float4*>(ap);
            a1 = *reinterpret_cast<const float4*>(ap + 4);
        } else {
            a0 = make_float4(0.f,0.f,0.f,0.f); a1 = a0;
        }
        b0 = *reinterpret_cast<const float4*>(&W[(size_t)bk * Dout + colBase + bc]);
    }
    As[0][akc+0][ar] = a0.x; As[0][akc+1][ar] = a0.y;
    As[0][akc+2][ar] = a0.z; As[0][akc+3][ar] = a0.w;
    As[0][akc+4][ar] = a1.x; As[0][akc+5][ar] = a1.y;
    As[0][akc+6][ar] = a1.z; As[0][akc+7][ar] = a1.w;
    *reinterpret_cast<float4*>(&Bs[0][bk][bc]) = b0;
    __syncthreads();

    int cur = 0;
    for (int kt = 0; kt < KT; kt++) {
        if (kt + 1 < KT) {
            int k0 = (kt + 1) * 16;
            int grow = rowBase + ar;
            if (grow < N_NODES) {
                const float* ap = &A[(size_t)grow * K + k0 + akc];
                a0 = *reinterpret_cast<const float4*>(ap);
                a1 = *reinterpret_cast<const float4*>(ap + 4);
            } else {
                a0 = make_float4(0.f,0.f,0.f,0.f); a1 = a0;
            }
            b0 = *reinterpret_cast<const float4*>(&W[(size_t)(k0 + bk) * Dout + colBase + bc]);
        }
        #pragma unroll
        for (int k = 0; k < 16; k++) {
            // a: 8 consecutive rows as 4 packed b64 (LDS.128 x2)
            ulonglong2 ap0 = *reinterpret_cast<const ulonglong2*>(&As[cur][k][ty * 8]);
            ulonglong2 ap1 = *reinterpret_cast<const ulonglong2*>(&As[cur][k][ty * 8 + 4]);
            unsigned long long apk[4] = {ap0.x, ap0.y, ap1.x, ap1.y};
            // b: 4 cols, replicate each into a packed pair
            float4 bv = *reinterpret_cast<const float4*>(&Bs[cur][k][tx * 4]);
            unsigned long long brep[4] = {
                pack2(__float_as_uint(bv.x), __float_as_uint(bv.x)),
                pack2(__float_as_uint(bv.y), __float_as_uint(bv.y)),
                pack2(__float_as_uint(bv.z), __float_as_uint(bv.z)),
                pack2(__float_as_uint(bv.w), __float_as_uint(bv.w))
            };
            #pragma unroll
            for (int ip = 0; ip < 4; ip++)
                #pragma unroll
                for (int j = 0; j < 4; j++)
                    ffma2(acc[ip][j], apk[ip], brep[j]);
        }
        if (kt + 1 < KT) {
            int nxt = cur ^ 1;
            As[nxt][akc+0][ar] = a0.x; As[nxt][akc+1][ar] = a0.y;
            As[nxt][akc+2][ar] = a0.z; As[nxt][akc+3][ar] = a0.w;
            As[nxt][akc+4][ar] = a1.x; As[nxt][akc+5][ar] = a1.y;
            As[nxt][akc+6][ar] = a1.z; As[nxt][akc+7][ar] = a1.w;
            *reinterpret_cast<float4*>(&Bs[nxt][bk][bc]) = b0;
            __syncthreads();
            cur = nxt;
        }
    }

    #pragma unroll
    for (int ip = 0; ip < 4; ip++) {
        int r0 = rowBase + ty * 8 + 2 * ip;
        float4 v0, v1;
        float* vp0 = &v0.x;
        float* vp1 = &v1.x;
        #pragma unroll
        for (int j = 0; j < 4; j++) {
            unsigned int lo, hi;
            unpack2(acc[ip][j], lo, hi);
            float xlo = __uint_as_float(lo);
            float xhi = __uint_as_float(hi);
            if (bias) {
                float b = bias[colBase + tx * 4 + j];
                xlo += b; xhi += b;
            }
            if (ACT == 1) { xlo = fmaxf(xlo, 0.f); xhi = fmaxf(xhi, 0.f); }
            vp0[j] = xlo; vp1[j] = xhi;
        }
        if (r0 < N_NODES)
            *reinterpret_cast<float4*>(&C[(size_t)r0 * Dout + colBase + tx * 4]) = v0;
        if (r0 + 1 < N_NODES)
            *reinterpret_cast<float4*>(&C[(size_t)(r0 + 1) * Dout + colBase + tx * 4]) = v1;
    }
}

// ---------------- Aggregation D=64: lane owns float2 ----------------
template <int ACT>  // 0 none, 1 relu, 2 sigmoid
__global__ void __launch_bounds__(256) agg64_kernel(
    const float* __restrict__ in, float* __restrict__ out,
    const float* __restrict__ bias) {
    int warp = (blockIdx.x * blockDim.x + threadIdx.x) >> 5;
    if (warp >= N_NODES) return;
    int lane = threadIdx.x & 31;
    const int off = lane * 2;

    float s = g_ns[warp];
    float2 self = *reinterpret_cast<const float2*>(in + (size_t)warp * 64 + off);
    float ax = s * self.x, ay = s * self.y;

    int e = g_rowbeg[warp], end = g_rowend[warp];
    for (; e + 4 <= end; e += 4) {
        unsigned long long e0 = g_edge[e],   e1 = g_edge[e+1];
        unsigned long long e2 = g_edge[e+2], e3 = g_edge[e+3];
        int s0 = (int)(unsigned int)e0, s1 = (int)(unsigned int)e1;
        int s2 = (int)(unsigned int)e2, s3 = (int)(unsigned int)e3;
        float w0 = __uint_as_float((unsigned int)(e0 >> 32));
        float w1 = __uint_as_float((unsigned int)(e1 >> 32));
        float w2 = __uint_as_float((unsigned int)(e2 >> 32));
        float w3 = __uint_as_float((unsigned int)(e3 >> 32));
        float2 p0 = *reinterpret_cast<const float2*>(in + (size_t)s0 * 64 + off);
        float2 p1 = *reinterpret_cast<const float2*>(in + (size_t)s1 * 64 + off);
        float2 p2 = *reinterpret_cast<const float2*>(in + (size_t)s2 * 64 + off);
        float2 p3 = *reinterpret_cast<const float2*>(in + (size_t)s3 * 64 + off);
        ax += w0 * p0.x; ay += w0 * p0.y;
        ax += w1 * p1.x; ay += w1 * p1.y;
        ax += w2 * p2.x; ay += w2 * p2.y;
        ax += w3 * p3.x; ay += w3 * p3.y;
    }
    for (; e < end; e++) {
        unsigned long long ee = g_edge[e];
        int si = (int)(unsigned int)ee;
        float w = __uint_as_float((unsigned int)(ee >> 32));
        float2 p = *reinterpret_cast<const float2*>(in + (size_t)si * 64 + off);
        ax += w * p.x; ay += w * p.y;
    }

    if (bias) {
        const float2 b = *reinterpret_cast<const float2*>(bias + off);
        ax += b.x; ay += b.y;
    }
    if (ACT == 1) { ax = fmaxf(ax, 0.f); ay = fmaxf(ay, 0.f); }
    if (ACT == 2) {
        ax = 1.0f / (1.0f + expf(-ax));
        ay = 1.0f / (1.0f + expf(-ay));
    }
    *reinterpret_cast<float2*>(out + (size_t)warp * 64 + off) = make_float2(ax, ay);
}

// ---------------- Aggregation D=128: lane owns float4 ----------------
template <int ACT>
__global__ void __launch_bounds__(256) agg128_kernel(
    const float* __restrict__ in, float* __restrict__ out,
    const float* __restrict__ bias) {
    int warp = (blockIdx.x * blockDim.x + threadIdx.x) >> 5;
    if (warp >= N_NODES) return;
    int lane = threadIdx.x & 31;
    const int off = lane * 4;

    float s = g_ns[warp];
    float4 self = *reinterpret_cast<const float4*>(in + (size_t)warp * 128 + off);
    float ax = s*self.x, ay = s*self.y, az = s*self.z, aw = s*self.w;

    int e = g_rowbeg[warp], end = g_rowend[warp];
    for (; e + 4 <= end; e += 4) {
        unsigned long long e0 = g_edge[e],   e1 = g_edge[e+1];
        unsigned long long e2 = g_edge[e+2], e3 = g_edge[e+3];
        int s0 = (int)(unsigned int)e0, s1 = (int)(unsigned int)e1;
        int s2 = (int)(unsigned int)e2, s3 = (int)(unsigned int)e3;
        float w0 = __uint_as_float((unsigned int)(e0 >> 32));
        float w1 = __uint_as_float((unsigned int)(e1 >> 32));
        float w2 = __uint_as_float((unsigned int)(e2 >> 32));
        float w3 = __uint_as_float((unsigned int)(e3 >> 32));
        float4 p0 = *reinterpret_cast<const float4*>(in + (size_t)s0 * 128 + off);
        float4 p1 = *reinterpret_cast<const float4*>(in + (size_t)s1 * 128 + off);
        float4 p2 = *reinterpret_cast<const float4*>(in + (size_t)s2 * 128 + off);
        float4 p3 = *reinterpret_cast<const float4*>(in + (size_t)s3 * 128 + off);
        ax += w0*p0.x; ay += w0*p0.y; az += w0*p0.z; aw += w0*p0.w;
        ax += w1*p1.x; ay += w1*p1.y; az += w1*p1.z; aw += w1*p1.w;
        ax += w2*p2.x; ay += w2*p2.y; az += w2*p2.z; aw += w2*p2.w;
        ax += w3*p3.x; ay += w3*p3.y; az += w3*p3.z; aw += w3*p3.w;
    }
    for (; e < end; e++) {
        unsigned long long ee = g_edge[e];
        int si = (int)(unsigned int)ee;
        float w = __uint_as_float((unsigned int)(ee >> 32));
        float4 p = *reinterpret_cast<const float4*>(in + (size_t)si * 128 + off);
        ax += w*p.x; ay += w*p.y; az += w*p.z; aw += w*p.w;
    }

    if (bias) {
        const float4 b = *reinterpret_cast<const float4*>(bias + off);
        ax += b.x; ay += b.y; az += b.z; aw += b.w;
    }
    if (ACT == 1) {
        ax = fmaxf(ax, 0.f); ay = fmaxf(ay, 0.f);
        az = fmaxf(az, 0.f); aw = fmaxf(aw, 0.f);
    }
    if (ACT == 2) {
        ax = 1.0f/(1.0f+expf(-ax)); ay = 1.0f/(1.0f+expf(-ay));
        az = 1.0f/(1.0f+expf(-az)); aw = 1.0f/(1.0f+expf(-aw));
    }
    *reinterpret_cast<float4*>(out + (size_t)warp * 128 + off) = make_float4(ax, ay, az, aw);
}

// ---------------- launch ----------------
extern "C" void kernel_launch(void* const* d_in, const int* in_sizes, int n_in,
                              void* d_out, int out_size) {
    const float* x  = (const float*)d_in[0];
    const int*   ei = (const int*)d_in[1];   // int32! (JAX x64 disabled)
    const float* W1 = (const float*)d_in[2],  *b1 = (const float*)d_in[3];
    const float* W2 = (const float*)d_in[4],  *b2 = (const float*)d_in[5];
    const float* W3 = (const float*)d_in[6],  *b3 = (const float*)d_in[7];
    const float* W4 = (const float*)d_in[8],  *b4 = (const float*)d_in[9];
    const float* W5 = (const float*)d_in[10], *b5 = (const float*)d_in[11];
    const float* W6 = (const float*)d_in[12], *b6 = (const float*)d_in[13];
    float* out = (float*)d_out;

    float *bufA, *bufB;
    cudaGetSymbolAddress((void**)&bufA, g_bufA);
    cudaGetSymbolAddress((void**)&bufB, g_bufB);

    const int TB = 256;
    const int nodeBlocks = (N_NODES + TB - 1) / TB;
    const int edgeBlocks = (N_EDGES + TB - 1) / TB;
    const int aggBlocks  = (N_NODES * 32 + TB - 1) / TB;
    const int gemmRows   = (N_NODES + 127) / 128;

    // ---- preprocessing: degrees + CSR by dst (scan-free) ----
    zero_cnt_kernel<<<nodeBlocks, TB>>>();
    hist_kernel<<<edgeBlocks, TB>>>(ei);
    alloc_kernel<<<nodeBlocks, TB>>>();
    scatter_kernel<<<edgeBlocks, TB>>>(ei);

    // L1: (128->64), aggregate AFTER matmul
    gemm_kernel<0><<<dim3(gemmRows, 1), TB>>>(x, W1, nullptr, bufA, 128, 64);
    agg64_kernel<1><<<aggBlocks, TB>>>(bufA, bufB, b1);

    // L2: (64->128), aggregate BEFORE matmul
    agg64_kernel<0><<<aggBlocks, TB>>>(bufB, bufA, nullptr);
    gemm_kernel<1><<<dim3(gemmRows, 2), TB>>>(bufA, W2, b2, bufB, 64, 128);

    // L3: (128->256), aggregate BEFORE matmul
    agg128_kernel<0><<<aggBlocks, TB>>>(bufB, bufA, nullptr);
    gemm_kernel<1><<<dim3(gemmRows, 4), TB>>>(bufA, W3, b3, bufB, 128, 256);

    // L4: (256->128), aggregate AFTER matmul
    gemm_kernel<0><<<dim3(gemmRows, 2), TB>>>(bufB, W4, nullptr, bufA, 256, 128);
    agg128_kernel<1><<<aggBlocks, TB>>>(bufA, bufB, b4);

    // L5: (128->64), aggregate AFTER matmul
    gemm_kernel<0><<<dim3(gemmRows, 1), TB>>>(bufB, W5, nullptr, bufA, 128, 64);
    agg64_kernel<1><<<aggBlocks, TB>>>(bufA, bufB, b5);

    // L6: (64->64), aggregate AFTER matmul, sigmoid, write d_out
    gemm_kernel<0><<<dim3(gemmRows, 1), TB>>>(bufB, W6, nullptr, bufA, 64, 64);
    agg64_kernel<2><<<aggBlocks, TB>>>(bufA, out, b6);
}